// round 12
// baseline (speedup 1.0000x reference)
#include <cuda_runtime.h>
#include <cuda_fp16.h>
#include <cstdint>

// ============================================================================
// Range_Fourier_Net: complex DFT as one fp16 mma.sync GEMM (fp32 accumulate).
//   A = [x_re | x_im] read DIRECTLY as fp32, converted to fp16 in the GEMM
//       producer (prep_a kernel eliminated — mainloop is HMMA-rate-bound at
//       ~14 cyc/HMMA/SMSP, so the LSU/cvt work rides in the slack).
//   g_B[2h]   = [ w_re[h] | -w_im[h] ]      (1024 x 1024 fp16)
//   g_B[2h+1] = [ w_im[h] |  w_re[h] ]
//   out = A @ B^T  -> rows are exactly the (..., h, re/im) output layout.
//
// 512 threads (16 warps, 4x4 grid, warp tile 64x32), ldmatrix.x4 fragment
// loads (conflict-free with 144B row stride), CTA tile 256x128x64,
// 3-stage pipeline (A: LDG+cvt+STS, B: cp.async).
// ============================================================================

static constexpr int M_TOTAL = 32768;
static constexpr int N_TOTAL = 1024;
static constexpr int BM = 256, BN = 128, BK = 64;
static constexpr int CHUNKS = 1024 / BK;                 // 16
static constexpr int STAGES = 3;
static constexpr int PAD_K  = 72;                        // halves -> 144 B rows
static constexpr int ROW_B  = PAD_K * 2;                 // 144
static constexpr int A_STAGE_BYTES = BM * ROW_B;         // 36864
static constexpr int B_STAGE_BYTES = BN * ROW_B;         // 18432
static constexpr int STAGE_BYTES   = A_STAGE_BYTES + B_STAGE_BYTES; // 55296
static constexpr int SMEM_BYTES    = STAGES * STAGE_BYTES;          // 165888

__device__ __align__(128) __half g_B[(size_t)N_TOTAL * 1024];  // 2 MB scratch

// ---------------------------------------------------------------------------
__device__ __forceinline__ uint32_t h2_bits(__half2 h) {
    uint32_t u;
    __builtin_memcpy(&u, &h, 4);
    return u;
}

__device__ __forceinline__ void cp16(uint32_t s, const void* g) {
    asm volatile("cp.async.cg.shared.global [%0], [%1], 16;" :: "r"(s), "l"(g));
}

__device__ __forceinline__ uint32_t smem_u32(const void* p) {
    uint32_t a;
    asm("{ .reg .u64 t; cvta.to.shared.u64 t, %1; cvt.u32.u64 %0, t; }"
        : "=r"(a) : "l"(p));
    return a;
}

__device__ __forceinline__ void ldmx4(uint32_t* r, uint32_t addr) {
    asm volatile("ldmatrix.sync.aligned.m8n8.x4.shared.b16 {%0,%1,%2,%3}, [%4];"
                 : "=r"(r[0]), "=r"(r[1]), "=r"(r[2]), "=r"(r[3]) : "r"(addr));
}

__device__ __forceinline__ void mma_f16(float* d, const uint32_t* a,
                                        uint32_t b0, uint32_t b1) {
    asm volatile(
        "mma.sync.aligned.m16n8k16.row.col.f32.f16.f16.f32 "
        "{%0,%1,%2,%3}, {%4,%5,%6,%7}, {%8,%9}, {%0,%1,%2,%3};"
        : "+f"(d[0]), "+f"(d[1]), "+f"(d[2]), "+f"(d[3])
        : "r"(a[0]), "r"(a[1]), "r"(a[2]), "r"(a[3]), "r"(b0), "r"(b1));
}

// ---------------------------------------------------------------------------
// prep B: interleaved complex weight matrix in fp16 (tiny: ~3 us).
// ---------------------------------------------------------------------------
__global__ void prep_b_kernel(const float* __restrict__ wr, const float* __restrict__ wi) {
    int t = blockIdx.x * blockDim.x + threadIdx.x;   // 0 .. 65535
    int h = t >> 7;
    int j = (t & 127) << 2;

    float4 r  = *reinterpret_cast<const float4*>(wr + (size_t)h * 512 + j);
    float4 im = *reinterpret_cast<const float4*>(wi + (size_t)h * 512 + j);

    uint2 rp, ip, np;
    rp.x = h2_bits(__floats2half2_rn(r.x, r.y));
    rp.y = h2_bits(__floats2half2_rn(r.z, r.w));
    ip.x = h2_bits(__floats2half2_rn(im.x, im.y));
    ip.y = h2_bits(__floats2half2_rn(im.z, im.w));
    np.x = h2_bits(__floats2half2_rn(-im.x, -im.y));
    np.y = h2_bits(__floats2half2_rn(-im.z, -im.w));

    __half* row_re = g_B + (size_t)(2 * h) * 1024;
    __half* row_im = row_re + 1024;
    *reinterpret_cast<uint2*>(row_re + j)       = rp;   // xr * wr
    *reinterpret_cast<uint2*>(row_re + 512 + j) = np;   // xi * -wi
    *reinterpret_cast<uint2*>(row_im + j)       = ip;   // xr * wi
    *reinterpret_cast<uint2*>(row_im + 512 + j) = rp;   // xi * wr
}

// ---------------------------------------------------------------------------
__global__ void __launch_bounds__(512, 1)
dft_gemm_kernel(const float* __restrict__ xr, const float* __restrict__ xi,
                float* __restrict__ out) {
    extern __shared__ __align__(128) char smem[];
    const uint32_t sbase = smem_u32(smem);

    const int tid  = threadIdx.x;
    const int wid  = tid >> 5;
    const int lane = tid & 31;
    const int g    = lane >> 2;
    const int t4   = lane & 3;

    const int warp_m = wid >> 2;         // 0..3 (64-row slice)
    const int warp_n = wid & 3;          // 0..3 (32-col slice)

    const int bid    = blockIdx.x;
    const int n_tile = bid & 7;          // adjacent bids share the A tile in L2
    const int m_tile = bid >> 3;
    const size_t m0  = (size_t)m_tile * BM;
    const int n0     = n_tile * BN;

    // ldmatrix lane addressing (within a stage):
    //  A .x4: lanes 0-15 -> tile rows (lane&15), lanes 16-31 same rows +16B (k+8)
    //  B .x4: lanes 0-7 -> n rows 0-7, 8-15 -> same +16B, 16-23 -> n 8-15, 24-31 +16B
    const uint32_t aLane = (uint32_t)((warp_m * 64 + (lane & 15)) * ROW_B
                                      + ((lane >> 4) & 1) * 16);
    const uint32_t bLane = (uint32_t)((warp_n * 32 + (lane & 7) + ((lane >> 4) & 1) * 8) * ROW_B
                                      + ((lane >> 3) & 1) * 16);

    // one BK=64 chunk.
    // B (128 x 64 fp16): cp.async from g_B, tracked by commit/wait_group.
    // A (256 x 64): LDG.128 fp32 from x, cvt to fp16, STS.128 (generic proxy;
    //   the per-chunk __syncthreads orders it for the consumers).
    auto produce = [&](int c, int st) {
        const uint32_t sA = sbase + st * STAGE_BYTES;
        const uint32_t sB = sA + A_STAGE_BYTES;

        const char* bbase = reinterpret_cast<const char*>(g_B)
                          + (size_t)n0 * 2048 + (size_t)c * 128;
#pragma unroll
        for (int p = 0; p < 2; p++) {                           // 128 rows x 8 x 16B
            int i = tid + (p << 9);
            int row = i >> 3, u = i & 7;
            cp16(sB + (uint32_t)(row * ROW_B + u * 16),
                 bbase + (size_t)row * 2048 + (u << 4));
        }
        asm volatile("cp.async.commit_group;" ::: "memory");

        // A: chunk c covers halves [64c, 64c+64) = 64 consecutive floats of
        // xr (c<8) or xi (c>=8). 2048 16B-segments; each thread does 4.
        const float* xb = (c < 8 ? xr : xi) + m0 * 512 + (size_t)(c & 7) * 64;
        float4 f[4][2];
#pragma unroll
        for (int p = 0; p < 4; p++) {                           // batch LDGs (MLP=8)
            int i = tid + (p << 9);
            int row = i >> 3, u = i & 7;
            const float4* src = reinterpret_cast<const float4*>(xb + (size_t)row * 512 + u * 8);
            f[p][0] = src[0];
            f[p][1] = src[1];
        }
#pragma unroll
        for (int p = 0; p < 4; p++) {
            int i = tid + (p << 9);
            int row = i >> 3, u = i & 7;
            uint4 h;
            h.x = h2_bits(__floats2half2_rn(f[p][0].x, f[p][0].y));
            h.y = h2_bits(__floats2half2_rn(f[p][0].z, f[p][0].w));
            h.z = h2_bits(__floats2half2_rn(f[p][1].x, f[p][1].y));
            h.w = h2_bits(__floats2half2_rn(f[p][1].z, f[p][1].w));
            *reinterpret_cast<uint4*>(smem + st * STAGE_BYTES + row * ROW_B + u * 16) = h;
        }
    };

    float acc[4][4][4];
#pragma unroll
    for (int mi = 0; mi < 4; mi++)
#pragma unroll
        for (int ni = 0; ni < 4; ni++)
#pragma unroll
            for (int q = 0; q < 4; q++) acc[mi][ni][q] = 0.0f;

    produce(0, 0);
    produce(1, 1);

    for (int c = 0; c < CHUNKS; c++) {
        const int st = c % STAGES;
        asm volatile("cp.async.wait_group 1;" ::: "memory");
        __syncthreads();
        if (c + 2 < CHUNKS) produce(c + 2, (c + 2) % STAGES);

        const uint32_t aBase = sbase + st * STAGE_BYTES + aLane;
        const uint32_t bBase = sbase + st * STAGE_BYTES + A_STAGE_BYTES + bLane;

#pragma unroll
        for (int kk = 0; kk < 4; kk++) {          // 4 x k16 steps
            uint32_t a[4][4];
#pragma unroll
            for (int mi = 0; mi < 4; mi++)
                ldmx4(a[mi], aBase + mi * 16 * ROW_B + kk * 32);
            uint32_t b[2][4];
#pragma unroll
            for (int np = 0; np < 2; np++)
                ldmx4(b[np], bBase + np * 16 * ROW_B + kk * 32);
#pragma unroll
            for (int mi = 0; mi < 4; mi++) {
                mma_f16(acc[mi][0], a[mi], b[0][0], b[0][1]);
                mma_f16(acc[mi][1], a[mi], b[0][2], b[0][3]);
                mma_f16(acc[mi][2], a[mi], b[1][0], b[1][1]);
                mma_f16(acc[mi][3], a[mi], b[1][2], b[1][3]);
            }
        }
    }

    // epilogue: C fragment rows g / g+8, cols 2*t4..2*t4+1 — float2 stores
    float* obase = out + (m0 + warp_m * 64 + g) * 1024 + n0 + warp_n * 32 + 2 * t4;
#pragma unroll
    for (int mi = 0; mi < 4; mi++) {
#pragma unroll
        for (int ni = 0; ni < 4; ni++) {
            float2 lo = make_float2(acc[mi][ni][0], acc[mi][ni][1]);
            float2 hi = make_float2(acc[mi][ni][2], acc[mi][ni][3]);
            *reinterpret_cast<float2*>(obase + (size_t)(mi * 16) * 1024 + ni * 8) = lo;
            *reinterpret_cast<float2*>(obase + (size_t)(mi * 16 + 8) * 1024 + ni * 8) = hi;
        }
    }
}

// ---------------------------------------------------------------------------
extern "C" void kernel_launch(void* const* d_in, const int* in_sizes, int n_in,
                              void* d_out, int out_size) {
    const float* x_re = (const float*)d_in[0];
    const float* x_im = (const float*)d_in[1];
    const float* w_re = (const float*)d_in[2];
    const float* w_im = (const float*)d_in[3];
    float* out = (float*)d_out;

    cudaFuncSetAttribute(dft_gemm_kernel,
                         cudaFuncAttributeMaxDynamicSharedMemorySize, SMEM_BYTES);

    prep_b_kernel<<<256, 256>>>(w_re, w_im);
    dft_gemm_kernel<<<(M_TOTAL / BM) * (N_TOTAL / BN), 512, SMEM_BYTES>>>(x_re, x_im, out);
}

// round 14
// speedup vs baseline: 1.3302x; 1.3302x over previous
#include <cuda_runtime.h>
#include <cuda_fp16.h>
#include <cstdint>

// ============================================================================
// Range_Fourier_Net: complex DFT as one fp16 mma.sync GEMM (fp32 accumulate).
//   g_A = [x_re | x_im] converted to fp16   (32768 x 1024)   [prep_a]
//   g_B[2h]   = [ w_re[h] | -w_im[h] ]      (1024 x 1024 fp16) [prep_b]
//   g_B[2h+1] = [ w_im[h] |  w_re[h] ]
//   out = A @ B^T  -> rows are exactly the (..., h, re/im) output layout.
//
// R12: CTA tile 128x128x64 (was 256x128), 256 threads, 110.6 KB SMEM ->
// TWO CTAs per SM. Cross-CTA overlap fills the per-chunk barrier/wait
// bubbles that capped the 1-CTA/SM version at tensor ~55%.
// 8 warps (2x4 grid, warp tile 64x32), ldmatrix.x4, 3-stage cp.async.
// ============================================================================

static constexpr int M_TOTAL = 32768;
static constexpr int N_TOTAL = 1024;
static constexpr int BM = 128, BN = 128, BK = 64;
static constexpr int CHUNKS = 1024 / BK;                 // 16
static constexpr int STAGES = 3;
static constexpr int PAD_K  = 72;                        // halves -> 144 B rows
static constexpr int ROW_B  = PAD_K * 2;                 // 144
static constexpr int A_STAGE_BYTES = BM * ROW_B;         // 18432
static constexpr int B_STAGE_BYTES = BN * ROW_B;         // 18432
static constexpr int STAGE_BYTES   = A_STAGE_BYTES + B_STAGE_BYTES; // 36864
static constexpr int SMEM_BYTES    = STAGES * STAGE_BYTES;          // 110592

__device__ __align__(128) __half g_A[(size_t)M_TOTAL * 1024];  // 64 MB scratch
__device__ __align__(128) __half g_B[(size_t)N_TOTAL * 1024];  // 2 MB scratch

// ---------------------------------------------------------------------------
__device__ __forceinline__ uint32_t h2_bits(__half2 h) {
    uint32_t u;
    __builtin_memcpy(&u, &h, 4);
    return u;
}

__device__ __forceinline__ void cp16(uint32_t s, const void* g) {
    asm volatile("cp.async.cg.shared.global [%0], [%1], 16;" :: "r"(s), "l"(g));
}

__device__ __forceinline__ uint32_t smem_u32(const void* p) {
    uint32_t a;
    asm("{ .reg .u64 t; cvta.to.shared.u64 t, %1; cvt.u32.u64 %0, t; }"
        : "=r"(a) : "l"(p));
    return a;
}

__device__ __forceinline__ void ldmx4(uint32_t* r, uint32_t addr) {
    asm volatile("ldmatrix.sync.aligned.m8n8.x4.shared.b16 {%0,%1,%2,%3}, [%4];"
                 : "=r"(r[0]), "=r"(r[1]), "=r"(r[2]), "=r"(r[3]) : "r"(addr));
}

__device__ __forceinline__ void mma_f16(float* d, const uint32_t* a,
                                        uint32_t b0, uint32_t b1) {
    asm volatile(
        "mma.sync.aligned.m16n8k16.row.col.f32.f16.f16.f32 "
        "{%0,%1,%2,%3}, {%4,%5,%6,%7}, {%8,%9}, {%0,%1,%2,%3};"
        : "+f"(d[0]), "+f"(d[1]), "+f"(d[2]), "+f"(d[3])
        : "r"(a[0]), "r"(a[1]), "r"(a[2]), "r"(a[3]), "r"(b0), "r"(b1));
}

// ---------------------------------------------------------------------------
// prep A: convert [x_re | x_im] rows to fp16, concatenated into g_A.
// ---------------------------------------------------------------------------
__global__ void prep_a_kernel(const float* __restrict__ xr, const float* __restrict__ xi) {
    size_t t   = (size_t)blockIdx.x * blockDim.x + threadIdx.x;  // 0 .. 4194303
    size_t row = t >> 7;
    int    c   = (int)(t & 127) << 2;

    float4 r = *reinterpret_cast<const float4*>(xr + row * 512 + c);
    float4 i = *reinterpret_cast<const float4*>(xi + row * 512 + c);

    uint2 rp, ip;
    rp.x = h2_bits(__floats2half2_rn(r.x, r.y));
    rp.y = h2_bits(__floats2half2_rn(r.z, r.w));
    ip.x = h2_bits(__floats2half2_rn(i.x, i.y));
    ip.y = h2_bits(__floats2half2_rn(i.z, i.w));

    __half* arow = g_A + row * 1024;
    *reinterpret_cast<uint2*>(arow + c)       = rp;
    *reinterpret_cast<uint2*>(arow + 512 + c) = ip;
}

// ---------------------------------------------------------------------------
// prep B: interleaved complex weight matrix in fp16.
// ---------------------------------------------------------------------------
__global__ void prep_b_kernel(const float* __restrict__ wr, const float* __restrict__ wi) {
    int t = blockIdx.x * blockDim.x + threadIdx.x;   // 0 .. 65535
    int h = t >> 7;
    int j = (t & 127) << 2;

    float4 r  = *reinterpret_cast<const float4*>(wr + (size_t)h * 512 + j);
    float4 im = *reinterpret_cast<const float4*>(wi + (size_t)h * 512 + j);

    uint2 rp, ip, np;
    rp.x = h2_bits(__floats2half2_rn(r.x, r.y));
    rp.y = h2_bits(__floats2half2_rn(r.z, r.w));
    ip.x = h2_bits(__floats2half2_rn(im.x, im.y));
    ip.y = h2_bits(__floats2half2_rn(im.z, im.w));
    np.x = h2_bits(__floats2half2_rn(-im.x, -im.y));
    np.y = h2_bits(__floats2half2_rn(-im.z, -im.w));

    __half* row_re = g_B + (size_t)(2 * h) * 1024;
    __half* row_im = row_re + 1024;
    *reinterpret_cast<uint2*>(row_re + j)       = rp;   // xr * wr
    *reinterpret_cast<uint2*>(row_re + 512 + j) = np;   // xi * -wi
    *reinterpret_cast<uint2*>(row_im + j)       = ip;   // xr * wi
    *reinterpret_cast<uint2*>(row_im + 512 + j) = rp;   // xi * wr
}

// ---------------------------------------------------------------------------
__global__ void __launch_bounds__(256, 2)
dft_gemm_kernel(float* __restrict__ out) {
    extern __shared__ __align__(128) char smem[];
    const uint32_t sbase = smem_u32(smem);

    const int tid  = threadIdx.x;
    const int wid  = tid >> 5;
    const int lane = tid & 31;
    const int g    = lane >> 2;
    const int t4   = lane & 3;

    const int warp_m = wid >> 2;         // 0..1 (64-row slice)
    const int warp_n = wid & 3;          // 0..3 (32-col slice)

    const int bid    = blockIdx.x;
    const int n_tile = bid & 7;          // adjacent bids share the A tile in L2
    const int m_tile = bid >> 3;
    const size_t m0  = (size_t)m_tile * BM;
    const int n0     = n_tile * BN;

    // ldmatrix lane addressing (within a stage):
    //  A .x4: lanes 0-15 -> tile rows (lane&15), lanes 16-31 same rows +16B (k+8)
    //  B .x4: lanes 0-7 -> n rows 0-7, 8-15 -> same +16B, 16-23 -> n 8-15, 24-31 +16B
    const uint32_t aLane = (uint32_t)((warp_m * 64 + (lane & 15)) * ROW_B
                                      + ((lane >> 4) & 1) * 16);
    const uint32_t bLane = (uint32_t)((warp_n * 32 + (lane & 7) + ((lane >> 4) & 1) * 8) * ROW_B
                                      + ((lane >> 3) & 1) * 16);

    // one BK=64 chunk: A 128x64 fp16 (128B/row), B 128x64 fp16
    auto produce = [&](int c, int st) {
        const uint32_t sA = sbase + st * STAGE_BYTES;
        const uint32_t sB = sA + A_STAGE_BYTES;
        const char* abase = reinterpret_cast<const char*>(g_A)
                          + m0 * 2048 + (size_t)c * 128;
#pragma unroll
        for (int p = 0; p < 4; p++) {                           // 128 rows x 8 x 16B
            int i = tid + (p << 8);
            int row = i >> 3, u = i & 7;
            cp16(sA + (uint32_t)(row * ROW_B + u * 16),
                 abase + (size_t)row * 2048 + (u << 4));
        }
        const char* bbase = reinterpret_cast<const char*>(g_B)
                          + (size_t)n0 * 2048 + (size_t)c * 128;
#pragma unroll
        for (int p = 0; p < 4; p++) {                           // 128 rows x 8 x 16B
            int i = tid + (p << 8);
            int row = i >> 3, u = i & 7;
            cp16(sB + (uint32_t)(row * ROW_B + u * 16),
                 bbase + (size_t)row * 2048 + (u << 4));
        }
        asm volatile("cp.async.commit_group;" ::: "memory");
    };

    float acc[4][4][4];
#pragma unroll
    for (int mi = 0; mi < 4; mi++)
#pragma unroll
        for (int ni = 0; ni < 4; ni++)
#pragma unroll
            for (int q = 0; q < 4; q++) acc[mi][ni][q] = 0.0f;

    produce(0, 0);
    produce(1, 1);

    for (int c = 0; c < CHUNKS; c++) {
        const int st = c % STAGES;
        asm volatile("cp.async.wait_group 1;" ::: "memory");
        __syncthreads();
        if (c + 2 < CHUNKS) produce(c + 2, (c + 2) % STAGES);

        const uint32_t aBase = sbase + st * STAGE_BYTES + aLane;
        const uint32_t bBase = sbase + st * STAGE_BYTES + A_STAGE_BYTES + bLane;

#pragma unroll
        for (int kk = 0; kk < 4; kk++) {          // 4 x k16 steps
            uint32_t a[4][4];
#pragma unroll
            for (int mi = 0; mi < 4; mi++)
                ldmx4(a[mi], aBase + mi * 16 * ROW_B + kk * 32);
            uint32_t b[2][4];
#pragma unroll
            for (int np = 0; np < 2; np++)
                ldmx4(b[np], bBase + np * 16 * ROW_B + kk * 32);
#pragma unroll
            for (int mi = 0; mi < 4; mi++) {
                mma_f16(acc[mi][0], a[mi], b[0][0], b[0][1]);
                mma_f16(acc[mi][1], a[mi], b[0][2], b[0][3]);
                mma_f16(acc[mi][2], a[mi], b[1][0], b[1][1]);
                mma_f16(acc[mi][3], a[mi], b[1][2], b[1][3]);
            }
        }
    }

    // epilogue: C fragment rows g / g+8, cols 2*t4..2*t4+1 — float2 stores
    float* obase = out + (m0 + warp_m * 64 + g) * 1024 + n0 + warp_n * 32 + 2 * t4;
#pragma unroll
    for (int mi = 0; mi < 4; mi++) {
#pragma unroll
        for (int ni = 0; ni < 4; ni++) {
            float2 lo = make_float2(acc[mi][ni][0], acc[mi][ni][1]);
            float2 hi = make_float2(acc[mi][ni][2], acc[mi][ni][3]);
            *reinterpret_cast<float2*>(obase + (size_t)(mi * 16) * 1024 + ni * 8) = lo;
            *reinterpret_cast<float2*>(obase + (size_t)(mi * 16 + 8) * 1024 + ni * 8) = hi;
        }
    }
}

// ---------------------------------------------------------------------------
extern "C" void kernel_launch(void* const* d_in, const int* in_sizes, int n_in,
                              void* d_out, int out_size) {
    const float* x_re = (const float*)d_in[0];
    const float* x_im = (const float*)d_in[1];
    const float* w_re = (const float*)d_in[2];
    const float* w_im = (const float*)d_in[3];
    float* out = (float*)d_out;

    cudaFuncSetAttribute(dft_gemm_kernel,
                         cudaFuncAttributeMaxDynamicSharedMemorySize, SMEM_BYTES);

    prep_a_kernel<<<16384, 256>>>(x_re, x_im);
    prep_b_kernel<<<256, 256>>>(w_re, w_im);
    dft_gemm_kernel<<<(M_TOTAL / BM) * (N_TOTAL / BN), 256, SMEM_BYTES>>>(out);
}